// round 11
// baseline (speedup 1.0000x reference)
#include <cuda_runtime.h>

// out[b,o,d,h,w] = bias[o] + sum_{i=d-2..d+2 in [0,10)} sum_{kh,kw}
//                    x[b,i,h+kh-2,w+kw-2] * W[o,i,i-d+2,kh,kw]
//
// Inputs: x[32,10,128,128] f32, W[10,10,5,5,5] f32, b[10] f32
// Output: [32,10,10,128,128] f32
//
// R11: FFMA2 engine, tightened. Persistent 592 CTAs (148 SMs x observed
// 4-CTA residency) over tile-major (tile,d) jobs; weight slice for the NEXT
// job register-prefetched during compute (1 barrier/job); weights padded to
// 12 floats per kw so loads are LDS.128; x rows via 2x LDS.128 (pitch 40).

#define HW 128
#define NCTAS 592
#define NJOBS 10240            // 1024 tiles (32b x 8ht x 4wt) * 10 d

typedef unsigned long long u64;

#define FMA2(d_, a_, b_, c_) \
    asm("fma.rn.f32x2 %0, %1, %2, %3;" : "=l"(d_) : "l"(a_), "l"(b_), "l"(c_))
#define PACK2(out_, lo_, hi_) \
    asm("mov.b64 %0, {%1, %2};" : "=l"(out_) : "f"(lo_), "f"(hi_))
#define UNPACK2(lo_, hi_, in_) \
    asm("mov.b64 {%0, %1}, %2;" : "=f"(lo_), "=f"(hi_) : "l"(in_))

// Repacked weights: [d][ip][kh][kw][12]  (j<10 -> W[o=j, i, ip, kh, kw],
// zero for invalid i and for pad j=10,11). 48B kw-rows -> LDS.128-friendly.
#define WROW 12
#define WSLICE (5 * 5 * 5 * WROW)          // 1500 floats per d
__device__ float g_Wr[10 * WSLICE];

__global__ void repack_kernel(const float* __restrict__ W) {
    int idx = blockIdx.x * blockDim.x + threadIdx.x;
    if (idx >= 10 * WSLICE) return;
    int j    = idx % WROW;
    int rest = idx / WROW;
    int kw = rest % 5; rest /= 5;
    int kh = rest % 5; rest /= 5;
    int ip = rest % 5;
    int d  = rest / 5;
    int i = d + ip - 2;
    float v = 0.0f;
    if (j < 10 && i >= 0 && i < 10)
        v = W[j * 1250 + i * 125 + ip * 25 + kh * 5 + kw];
    g_Wr[idx] = v;
}

// SMEM: xs 10ch x 20rows x pitch40 | ws double buffer 2x1500 | bs 10
#define XPITCH 40
#define XS_FLOATS (10 * 20 * XPITCH)        // 8000 (32000B, 16B aligned)
#define SMEM_FLOATS (XS_FLOATS + 2 * WSLICE + 10)   // 11010 fl = 44040 B

__global__ __launch_bounds__(128, 4) void conv_main(
    const float* __restrict__ x,
    const float* __restrict__ bias,
    float* __restrict__ out)
{
    extern __shared__ float smem[];
    float* xs = smem;
    float* wsbuf = smem + XS_FLOATS;     // byte 32000: both slices 16B aligned
    float* bs = wsbuf + 2 * WSLICE;      // byte 44000

    const int tid = threadIdx.x;
    const int cta = blockIdx.x;

    // contiguous job range: NJOBS = NCTAS*17 + 176
    const int q = NJOBS / NCTAS;
    const int r = NJOBS % NCTAS;
    int job = cta * q + ((cta < r) ? cta : r);
    const int jobEnd = job + q + (cta < r ? 1 : 0);

    if (tid < 10) bs[tid] = bias[tid];

    const int hh = tid >> 3;             // 0..15
    const int ww = (tid & 7) << 2;       // 0..28

    // ---- prologue: stage first job's weight slice into buf0 ----
    {
        const float* src = g_Wr + (job % 10) * WSLICE;
        for (int k = tid; k < WSLICE; k += 128)
            wsbuf[k] = __ldg(src + k);
    }
    // visibility via the tile-change barrier of the first job (always taken)

    int curTile = -1;
    int h0 = 0, w0 = 0;
    int buf = 0;
    const float* xb = x;
    float* outp = out;

    for (; job < jobEnd; ++job, buf ^= 1) {
        const int d  = job % 10;
        const int tj = job / 10;

        // ---- tile change: reload xs, then barrier ----
        if (tj != curTile) {
            curTile = tj;
            const int b = tj >> 5;
            const int t = tj & 31;
            h0 = (t >> 2) << 4;          // 8 htiles of 16 rows
            w0 = (t & 3) << 5;           // 4 wtiles of 32 cols
            xb = x + b * (10 * HW * HW);
            outp = out + b * (100 * HW * HW) + (h0 + hh) * HW + (w0 + ww);

            for (int idx = tid; idx < 10 * 20 * 36; idx += 128) {
                int c   = idx / 720;
                int rem = idx - c * 720;
                int rr_ = rem / 36;
                int col = rem - rr_ * 36;
                int gh = h0 + rr_ - 2;
                int gw = w0 + col - 2;
                float v = 0.0f;
                if ((unsigned)gh < 128u && (unsigned)gw < 128u)
                    v = __ldg(xb + c * (HW * HW) + gh * HW + gw);
                xs[(c * 20 + rr_) * XPITCH + col] = v;
            }
            __syncthreads();   // xs + staged ws visible to all warps
        }

        const float* ws = wsbuf + buf * WSLICE;

        // ---- register-prefetch NEXT job's weight slice (overlaps compute) --
        float wpf[12];
        const bool pf = (job + 1 < jobEnd);
        if (pf) {
            const float* src = g_Wr + ((job + 1) % 10) * WSLICE;
            #pragma unroll
            for (int k = 0; k < 11; ++k) wpf[k] = __ldg(src + tid + k * 128);
            wpf[11] = (tid + 11 * 128 < WSLICE) ? __ldg(src + tid + 11 * 128) : 0.0f;
        }

        u64 acc[5][4];
        {
            const u64* b2 = (const u64*)bs;
            #pragma unroll
            for (int o2 = 0; o2 < 5; ++o2) {
                u64 bv = b2[o2];
                #pragma unroll
                for (int p = 0; p < 4; ++p) acc[o2][p] = bv;
            }
        }

        const int iLo = (d > 2) ? d - 2 : 0;
        const int iHi = (d < 7) ? d + 2 : 9;

        for (int i = iLo; i <= iHi; ++i) {
            const int ip = i - d + 2;
            const float* wbase = ws + ip * (5 * 5 * WROW);
            const float* xbase = xs + (i * 20 + hh) * XPITCH + ww;

            #pragma unroll
            for (int kh = 0; kh < 5; ++kh) {
                // x row: two LDS.128 (16B aligned: ww%4==0, pitch 40)
                const float4* x4 = (const float4*)(xbase + kh * XPITCH);
                float4 va = x4[0];
                float4 vb = x4[1];
                float rv[8] = {va.x, va.y, va.z, va.w, vb.x, vb.y, vb.z, vb.w};
                u64 rr[8];
                #pragma unroll
                for (int tt = 0; tt < 8; ++tt) PACK2(rr[tt], rv[tt], rv[tt]);

                const float* wk = wbase + kh * (5 * WROW);
                #pragma unroll
                for (int kw = 0; kw < 5; ++kw) {
                    // 5 o-pairs: 2x LDS.128 + 1x LDS.64 (row is 16B aligned)
                    const u64* w2 = (const u64*)(wk + kw * WROW);
                    u64 w[5];
                    {
                        const float4* wq = (const float4*)w2;
                        float4 q0 = wq[0], q1 = wq[1];
                        u64 t0, t1, t2, t3;
                        PACK2(t0, q0.x, q0.y);
                        PACK2(t1, q0.z, q0.w);
                        PACK2(t2, q1.x, q1.y);
                        PACK2(t3, q1.z, q1.w);
                        w[0] = t0; w[1] = t1; w[2] = t2; w[3] = t3;
                        w[4] = w2[4];
                    }
                    #pragma unroll
                    for (int o2 = 0; o2 < 5; ++o2) {
                        #pragma unroll
                        for (int p = 0; p < 4; ++p)
                            FMA2(acc[o2][p], w[o2], rr[kw + p], acc[o2][p]);
                    }
                }
            }
        }

        // ---- store: two float4 per o-pair ----
        #pragma unroll
        for (int o2 = 0; o2 < 5; ++o2) {
            float lo0, hi0, lo1, hi1, lo2, hi2, lo3, hi3;
            UNPACK2(lo0, hi0, acc[o2][0]);
            UNPACK2(lo1, hi1, acc[o2][1]);
            UNPACK2(lo2, hi2, acc[o2][2]);
            UNPACK2(lo3, hi3, acc[o2][3]);
            float4 sa = make_float4(lo0, lo1, lo2, lo3);
            float4 sb = make_float4(hi0, hi1, hi2, hi3);
            *(float4*)(outp + ((2 * o2) * 10 + d) * (HW * HW))     = sa;
            *(float4*)(outp + ((2 * o2 + 1) * 10 + d) * (HW * HW)) = sb;
        }

        // ---- commit prefetched slice to the other buffer; single barrier ----
        if (pf) {
            float* dst = wsbuf + (buf ^ 1) * WSLICE;
            #pragma unroll
            for (int k = 0; k < 11; ++k) dst[tid + k * 128] = wpf[k];
            if (tid + 11 * 128 < WSLICE) dst[tid + 11 * 128] = wpf[11];
        }
        __syncthreads();   // orders: compute/store(job) before xs/ws rewrite;
                           // staged ws visible for job+1
    }
}

extern "C" void kernel_launch(void* const* d_in, const int* in_sizes, int n_in,
                              void* d_out, int out_size) {
    const float* x    = (const float*)d_in[0];
    const float* W    = (const float*)d_in[1];
    const float* bias = (const float*)d_in[2];
    float* out = (float*)d_out;

    repack_kernel<<<59, 256>>>(W);

    const size_t smem_bytes = SMEM_FLOATS * sizeof(float);   // 44040
    cudaFuncSetAttribute(conv_main, cudaFuncAttributeMaxDynamicSharedMemorySize,
                         (int)smem_bytes);

    conv_main<<<NCTAS, 128, smem_bytes>>>(x, bias, out);
}

// round 12
// speedup vs baseline: 1.0355x; 1.0355x over previous
#include <cuda_runtime.h>

// out[b,o,d,h,w] = bias[o] + sum_{i=d-2..d+2 in [0,10)} sum_{kh,kw}
//                    x[b,i,h+kh-2,w+kw-2] * W[o,i,i-d+2,kh,kw]
//
// Inputs: x[32,10,128,128] f32, W[10,10,5,5,5] f32, b[10] f32
// Output: [32,10,10,128,128] f32
//
// R12 = R5 engine + two contained changes:
//  (1) weight LDS.64 loads software-pipelined across kw (load kw+1 before
//      kw's FFMA2s) to hide the 29-cyc smem latency behind the FMA stream;
//  (2) x pitch 37->40 so each row read is two aligned LDS.128.
// Weights remain o-contiguous LDS.64 broadcasts (pre-packed operand; the
// R11 lesson: never rebuild packs in registers).

#define NB 32
#define NC 10
#define HW 128

typedef unsigned long long u64;

#define FMA2(d_, a_, b_, c_) \
    asm("fma.rn.f32x2 %0, %1, %2, %3;" : "=l"(d_) : "l"(a_), "l"(b_), "l"(c_))
#define PACK2(out_, lo_, hi_) \
    asm("mov.b64 %0, {%1, %2};" : "=l"(out_) : "f"(lo_), "f"(hi_))
#define UNPACK2(lo_, hi_, in_) \
    asm("mov.b64 {%0, %1}, %2;" : "=f"(lo_), "=f"(hi_) : "l"(in_))

// Repacked weights: [d][ip][kh][kw][o], zero where i=d+ip-2 out of range.
__device__ float g_Wr[10 * 5 * 5 * 5 * 10];

__global__ void repack_kernel(const float* __restrict__ W) {
    int idx = blockIdx.x * blockDim.x + threadIdx.x;
    if (idx >= 12500) return;
    int o    = idx % 10;
    int rest = idx / 10;
    int kw = rest % 5; rest /= 5;
    int kh = rest % 5; rest /= 5;
    int ip = rest % 5;
    int d  = rest / 5;
    int i = d + ip - 2;
    float v = 0.0f;
    if (i >= 0 && i < 10)
        v = W[o * 1250 + i * 125 + ip * 25 + kh * 5 + kw];
    g_Wr[idx] = v;
}

// SMEM: xs 10ch x 20rows x pitch40 | ws 1250 | bs 10
#define XPITCH 40
#define XS_FLOATS (10 * 20 * XPITCH)        // 8000 (32000B)
#define WSLICE 1250
#define SMEM_FLOATS (XS_FLOATS + WSLICE + 10)   // 9260 fl = 37040 B

__global__ __launch_bounds__(128, 4) void conv_main(
    const float* __restrict__ x,
    const float* __restrict__ bias,
    float* __restrict__ out)
{
    extern __shared__ float smem[];
    float* xs = smem;
    float* ws = smem + XS_FLOATS;      // byte 32000, 16B aligned
    float* bs = ws + WSLICE;           // byte 37000, 8B aligned

    const int b  = blockIdx.x >> 5;
    const int t  = blockIdx.x & 31;
    const int h0 = (t >> 2) << 4;      // 8 htiles of 16 rows
    const int w0 = (t & 3) << 5;       // 4 wtiles of 32 cols
    const int tid = threadIdx.x;

    // ---- load x tile with halo: 10 ch x 20 rows x 36 cols (pitch 40) ----
    const float* xb = x + b * (NC * HW * HW);
    for (int idx = tid; idx < 10 * 20 * 36; idx += 128) {
        int c   = idx / 720;
        int rem = idx - c * 720;
        int r   = rem / 36;
        int col = rem - r * 36;
        int gh = h0 + r - 2;
        int gw = w0 + col - 2;
        float v = 0.0f;
        if ((unsigned)gh < 128u && (unsigned)gw < 128u)
            v = __ldg(xb + c * (HW * HW) + gh * HW + gw);
        xs[(c * 20 + r) * XPITCH + col] = v;
    }
    if (tid < 10) bs[tid] = bias[tid];
    // first in-loop barrier orders xs/bs writes before reads

    const int hh = tid >> 3;           // 0..15
    const int ww = (tid & 7) << 2;     // 0..28
    float* outp = out + b * (100 * HW * HW) + (h0 + hh) * HW + (w0 + ww);

    for (int d = 0; d < 10; ++d) {
        // ---- stage this d's weight slice (L1/L2-hot) ----
        {
            const float* src = g_Wr + d * WSLICE;
            for (int idx = tid; idx < WSLICE; idx += 128)
                ws[idx] = __ldg(src + idx);
        }
        __syncthreads();

        u64 acc[5][4];
        {
            const u64* b2 = (const u64*)bs;
            #pragma unroll
            for (int o2 = 0; o2 < 5; ++o2) {
                u64 bv = b2[o2];
                #pragma unroll
                for (int p = 0; p < 4; ++p) acc[o2][p] = bv;
            }
        }

        const int iLo = (d > 2) ? d - 2 : 0;
        const int iHi = (d < 7) ? d + 2 : 9;

        for (int i = iLo; i <= iHi; ++i) {
            const int ip = i - d + 2;
            const float* wbase = ws + ip * 250;            // 5kh x 5kw x 10o
            const float* xbase = xs + (i * 20 + hh) * XPITCH + ww;

            #pragma unroll
            for (int kh = 0; kh < 5; ++kh) {
                // x row: two aligned LDS.128
                const float4* x4 = (const float4*)(xbase + kh * XPITCH);
                float4 va = x4[0];
                float4 vb = x4[1];
                float rv[8] = {va.x, va.y, va.z, va.w, vb.x, vb.y, vb.z, vb.w};
                u64 rr[8];
                #pragma unroll
                for (int tt = 0; tt < 8; ++tt) PACK2(rr[tt], rv[tt], rv[tt]);

                const u64* wk2 = (const u64*)(wbase + kh * 50);   // 8B aligned

                // software-pipelined weight loads across kw
                u64 wc[5], wn[5];
                #pragma unroll
                for (int o2 = 0; o2 < 5; ++o2) wc[o2] = wk2[o2];   // kw = 0

                #pragma unroll
                for (int kw = 0; kw < 5; ++kw) {
                    if (kw < 4) {
                        #pragma unroll
                        for (int o2 = 0; o2 < 5; ++o2)
                            wn[o2] = wk2[(kw + 1) * 5 + o2];
                    }
                    #pragma unroll
                    for (int o2 = 0; o2 < 5; ++o2) {
                        #pragma unroll
                        for (int p = 0; p < 4; ++p)
                            FMA2(acc[o2][p], wc[o2], rr[kw + p], acc[o2][p]);
                    }
                    if (kw < 4) {
                        #pragma unroll
                        for (int o2 = 0; o2 < 5; ++o2) wc[o2] = wn[o2];
                    }
                }
            }
        }

        // ---- store: two float4 per o-pair ----
        #pragma unroll
        for (int o2 = 0; o2 < 5; ++o2) {
            float lo0, hi0, lo1, hi1, lo2, hi2, lo3, hi3;
            UNPACK2(lo0, hi0, acc[o2][0]);
            UNPACK2(lo1, hi1, acc[o2][1]);
            UNPACK2(lo2, hi2, acc[o2][2]);
            UNPACK2(lo3, hi3, acc[o2][3]);
            float4 sa = make_float4(lo0, lo1, lo2, lo3);
            float4 sb = make_float4(hi0, hi1, hi2, hi3);
            *(float4*)(outp + ((2 * o2) * 10 + d) * (HW * HW))     = sa;
            *(float4*)(outp + ((2 * o2 + 1) * 10 + d) * (HW * HW)) = sb;
        }

        __syncthreads();   // compute(d) done before ws overwrite at d+1
    }
}

extern "C" void kernel_launch(void* const* d_in, const int* in_sizes, int n_in,
                              void* d_out, int out_size) {
    const float* x    = (const float*)d_in[0];
    const float* W    = (const float*)d_in[1];
    const float* bias = (const float*)d_in[2];
    float* out = (float*)d_out;

    repack_kernel<<<49, 256>>>(W);

    const size_t smem_bytes = SMEM_FLOATS * sizeof(float);   // 37040
    cudaFuncSetAttribute(conv_main, cudaFuncAttributeMaxDynamicSharedMemorySize,
                         (int)smem_bytes);

    conv_main<<<NB * 32, 128, smem_bytes>>>(x, bias, out);
}

// round 13
// speedup vs baseline: 1.3688x; 1.3219x over previous
#include <cuda_runtime.h>

// out[b,o,d,h,w] = bias[o] + sum_{i=d-2..d+2 in [0,10)} sum_{kh,kw}
//                    x[b,i,h+kh-2,w+kw-2] * W[o,i,i-d+2,kh,kw]
//
// Inputs: x[32,10,128,128] f32, W[10,10,5,5,5] f32, b[10] f32
// Output: [32,10,10,128,128] f32
//
// R13: p=8 pixel strips in the proven R5 operand path (scalar x LDS at
// pitch 37, o-contiguous LDS.64 broadcast weights, NO float4 x loads).
// 256 threads cover a 64x32 tile; per (i,kh) unit the x window and weights
// amortize over 200 FFMA2 (issue density 1.28/FMA2 vs 1.43 at p=4).
// Persistent 296 CTAs (148x2) over 2560 tile-major (tile,d) jobs.

#define HW 128
#define NC 10
#define NCTAS 296
#define NJOBS 2560             // 256 tiles (32b x 2ht x 4wt) * 10 d

typedef unsigned long long u64;

#define FMA2(d_, a_, b_, c_) \
    asm("fma.rn.f32x2 %0, %1, %2, %3;" : "=l"(d_) : "l"(a_), "l"(b_), "l"(c_))
#define PACK2(out_, lo_, hi_) \
    asm("mov.b64 %0, {%1, %2};" : "=l"(out_) : "f"(lo_), "f"(hi_))
#define UNPACK2(lo_, hi_, in_) \
    asm("mov.b64 {%0, %1}, %2;" : "=f"(lo_), "=f"(hi_) : "l"(in_))

// Repacked weights: [d][ip][kh][kw][o], zero where i=d+ip-2 out of range.
__device__ float g_Wr[10 * 5 * 5 * 5 * 10];

__global__ void repack_kernel(const float* __restrict__ W) {
    int idx = blockIdx.x * blockDim.x + threadIdx.x;
    if (idx >= 12500) return;
    int o    = idx % 10;
    int rest = idx / 10;
    int kw = rest % 5; rest /= 5;
    int kh = rest % 5; rest /= 5;
    int ip = rest % 5;
    int d  = rest / 5;
    int i = d + ip - 2;
    float v = 0.0f;
    if (i >= 0 && i < 10)
        v = W[o * 1250 + i * 125 + ip * 25 + kh * 5 + kw];
    g_Wr[idx] = v;
}

// SMEM: xs 10ch x 68rows x pitch37 | ws 1250 | bs 10
#define XPITCH 37
#define XROWS  68                          // 64 + 4 halo
#define XS_FLOATS (10 * XROWS * XPITCH)    // 25160
#define WSLICE 1250
#define SMEM_FLOATS (XS_FLOATS + WSLICE + 10)   // 26420 fl = 105680 B

__global__ __launch_bounds__(256, 2) void conv_main(
    const float* __restrict__ x,
    const float* __restrict__ bias,
    float* __restrict__ out)
{
    extern __shared__ float smem[];
    float* xs = smem;
    float* ws = smem + XS_FLOATS;      // byte 100640, 8B aligned
    float* bs = ws + WSLICE;           // byte 105640, 8B aligned

    const int tid = threadIdx.x;
    const int cta = blockIdx.x;

    // contiguous job range: NJOBS = NCTAS*8 + 192
    const int q = NJOBS / NCTAS;
    const int r = NJOBS % NCTAS;
    int job = cta * q + ((cta < r) ? cta : r);
    const int jobEnd = job + q + (cta < r ? 1 : 0);

    if (tid < 10) bs[tid] = bias[tid];   // visible after first in-loop barrier

    const int hh = tid >> 2;             // 0..63
    const int ww = (tid & 3) << 3;       // 0,8,16,24

    int curTile = -1;
    float* outp = out;

    for (; job < jobEnd; ++job) {
        const int d  = job % 10;
        const int tj = job / 10;

        // ---- tile change: reload xs (prev job's reads ordered by trailing
        //      barrier; visibility via the stage-barrier below) ----
        if (tj != curTile) {
            curTile = tj;
            const int b = tj >> 3;
            const int t = tj & 7;
            const int h0 = (t >> 2) << 6;    // 2 htiles of 64 rows
            const int w0 = (t & 3) << 5;     // 4 wtiles of 32 cols
            const float* xb = x + b * (NC * HW * HW);
            outp = out + b * (100 * HW * HW) + (h0 + hh) * HW + (w0 + ww);

            for (int idx = tid; idx < 10 * XROWS * 36; idx += 256) {
                int c   = idx / (XROWS * 36);
                int rem = idx - c * (XROWS * 36);
                int rr_ = rem / 36;
                int col = rem - rr_ * 36;
                int gh = h0 + rr_ - 2;
                int gw = w0 + col - 2;
                float v = 0.0f;
                if ((unsigned)gh < 128u && (unsigned)gw < 128u)
                    v = __ldg(xb + c * (HW * HW) + gh * HW + gw);
                xs[(c * XROWS + rr_) * XPITCH + col] = v;
            }
        }

        // ---- stage this d's weight slice (L1/L2-hot) ----
        {
            const float* src = g_Wr + d * WSLICE;
            for (int idx = tid; idx < WSLICE; idx += 256)
                ws[idx] = __ldg(src + idx);
        }
        __syncthreads();

        u64 acc[5][8];
        {
            const u64* b2 = (const u64*)bs;
            #pragma unroll
            for (int o2 = 0; o2 < 5; ++o2) {
                u64 bv = b2[o2];
                #pragma unroll
                for (int p = 0; p < 8; ++p) acc[o2][p] = bv;
            }
        }

        const int iLo = (d > 2) ? d - 2 : 0;
        const int iHi = (d < 7) ? d + 2 : 9;

        for (int i = iLo; i <= iHi; ++i) {
            const int ip = i - d + 2;
            const float* wbase = ws + ip * 250;            // 5kh x 5kw x 10o
            const float* xbase = xs + (i * XROWS + hh) * XPITCH + ww;

            #pragma unroll
            for (int kh = 0; kh < 5; ++kh) {
                // scalar x window: 12 values cover kw(0..4)+px(0..7)
                const float* xr = xbase + kh * XPITCH;
                float rv[12];
                #pragma unroll
                for (int tt = 0; tt < 12; ++tt) rv[tt] = xr[tt];
                u64 rr[12];
                #pragma unroll
                for (int tt = 0; tt < 12; ++tt) PACK2(rr[tt], rv[tt], rv[tt]);

                const u64* wk2 = (const u64*)(wbase + kh * 50);   // 8B aligned
                #pragma unroll
                for (int kw = 0; kw < 5; ++kw) {
                    u64 w[5];
                    #pragma unroll
                    for (int o2 = 0; o2 < 5; ++o2) w[o2] = wk2[kw * 5 + o2];
                    #pragma unroll
                    for (int o2 = 0; o2 < 5; ++o2) {
                        #pragma unroll
                        for (int p = 0; p < 8; ++p)
                            FMA2(acc[o2][p], w[o2], rr[kw + p], acc[o2][p]);
                    }
                }
            }
        }

        // ---- store: 8 px per o => two float4 per o ----
        #pragma unroll
        for (int o2 = 0; o2 < 5; ++o2) {
            float lo[8], hi[8];
            #pragma unroll
            for (int p = 0; p < 8; ++p) UNPACK2(lo[p], hi[p], acc[o2][p]);
            float* pa = outp + ((2 * o2) * 10 + d) * (HW * HW);
            float* pb = outp + ((2 * o2 + 1) * 10 + d) * (HW * HW);
            *(float4*)(pa)     = make_float4(lo[0], lo[1], lo[2], lo[3]);
            *(float4*)(pa + 4) = make_float4(lo[4], lo[5], lo[6], lo[7]);
            *(float4*)(pb)     = make_float4(hi[0], hi[1], hi[2], hi[3]);
            *(float4*)(pb + 4) = make_float4(hi[4], hi[5], hi[6], hi[7]);
        }

        __syncthreads();   // compute/store(job) done before xs/ws rewrite
    }
}

extern "C" void kernel_launch(void* const* d_in, const int* in_sizes, int n_in,
                              void* d_out, int out_size) {
    const float* x    = (const float*)d_in[0];
    const float* W    = (const float*)d_in[1];
    const float* bias = (const float*)d_in[2];
    float* out = (float*)d_out;

    repack_kernel<<<49, 256>>>(W);

    const size_t smem_bytes = SMEM_FLOATS * sizeof(float);   // 105680
    cudaFuncSetAttribute(conv_main, cudaFuncAttributeMaxDynamicSharedMemorySize,
                         (int)smem_bytes);

    conv_main<<<NCTAS, 256, smem_bytes>>>(x, bias, out);
}